// round 3
// baseline (speedup 1.0000x reference)
#include <cuda_runtime.h>
#include <cstdint>

// GraphReversePool: out[b, v] = x[b, v2c[v]]
//   x   : [BATCH, N_CLUSTERS] fp32   (d_in[0])
//   v2c : [VERTICES] int32           (d_in[1])
//   out : [BATCH, VERTICES] fp32
//
// R3: rows interleaved in smem as float2{r0[c], r1[c]} -> one LDS.64 serves
// both batch rows (2-phase 16-lane conflict model beats 2x LDS.32), plus
// software-pipelined v2c prefetch to hide L2 latency under the store stream.

#define BLOCK_THREADS 1024

__global__ __launch_bounds__(BLOCK_THREADS, 1)
void graph_reverse_pool_kernel(const float* __restrict__ x,
                               const int*   __restrict__ v2c,
                               float*       __restrict__ out,
                               int batch, int n_clusters, int n_vertices)
{
    extern __shared__ float smem[];   // interleaved: smem[2c]=r0[c], smem[2c+1]=r1[c]

    const int b0 = blockIdx.x * 2;
    const int b1 = b0 + 1;
    const bool have_b1 = (b1 < batch);

    const int nc4 = n_clusters >> 2;       // 6250 (exact for 25000)

    // ---- Stage: zip row0/row1 float4s into interleaved float2 layout ----
    {
        const float4* __restrict__ x0 = reinterpret_cast<const float4*>(x + (size_t)b0 * n_clusters);
        float4* __restrict__ s4 = reinterpret_cast<float4*>(smem);
        if (have_b1) {
            const float4* __restrict__ x1 = reinterpret_cast<const float4*>(x + (size_t)b1 * n_clusters);
            for (int i = threadIdx.x; i < nc4; i += BLOCK_THREADS) {
                float4 a = x0[i];
                float4 b = x1[i];
                float4 lo = make_float4(a.x, b.x, a.y, b.y);
                float4 hi = make_float4(a.z, b.z, a.w, b.w);
                s4[2 * i]     = lo;
                s4[2 * i + 1] = hi;
            }
        } else {
            for (int i = threadIdx.x; i < nc4; i += BLOCK_THREADS) {
                float4 a = x0[i];
                float4 lo = make_float4(a.x, 0.f, a.y, 0.f);
                float4 hi = make_float4(a.z, 0.f, a.w, 0.f);
                s4[2 * i]     = lo;
                s4[2 * i + 1] = hi;
            }
        }
        // scalar tail over clusters (dead for 25000, kept for safety)
        for (int i = (nc4 << 2) + threadIdx.x; i < n_clusters; i += BLOCK_THREADS) {
            smem[2 * i]     = x[(size_t)b0 * n_clusters + i];
            smem[2 * i + 1] = have_b1 ? x[(size_t)b1 * n_clusters + i] : 0.f;
        }
    }
    __syncthreads();

    // ---- Gather: int4 v2c -> 4x LDS.64 -> 2x STG.128, prefetched ----
    const float2* __restrict__ s2 = reinterpret_cast<const float2*>(smem);
    const int4*   __restrict__ v2c4 = reinterpret_cast<const int4*>(v2c);
    float4* __restrict__ o0 = reinterpret_cast<float4*>(out + (size_t)b0 * n_vertices);
    float4* __restrict__ o1 = reinterpret_cast<float4*>(out + (size_t)b1 * n_vertices);

    const int nv4 = n_vertices >> 2;       // 25000 (exact for 100000)

    int v = threadIdx.x;
    if (have_b1) {
        if (v < nv4) {
            int4 c = v2c4[v];
            int vn = v + BLOCK_THREADS;
            while (vn < nv4) {
                const int4 cn = v2c4[vn];            // prefetch next indices
                float2 p0 = s2[c.x];
                float2 p1 = s2[c.y];
                float2 p2 = s2[c.z];
                float2 p3 = s2[c.w];
                o0[v] = make_float4(p0.x, p1.x, p2.x, p3.x);
                o1[v] = make_float4(p0.y, p1.y, p2.y, p3.y);
                v = vn; vn += BLOCK_THREADS;
                c = cn;
            }
            // final iteration
            float2 p0 = s2[c.x];
            float2 p1 = s2[c.y];
            float2 p2 = s2[c.z];
            float2 p3 = s2[c.w];
            o0[v] = make_float4(p0.x, p1.x, p2.x, p3.x);
            o1[v] = make_float4(p0.y, p1.y, p2.y, p3.y);
        }
        // scalar vertex tail (dead for 100000)
        for (int t = (nv4 << 2) + threadIdx.x; t < n_vertices; t += BLOCK_THREADS) {
            const int c = v2c[t];
            out[(size_t)b0 * n_vertices + t] = s2[c].x;
            out[(size_t)b1 * n_vertices + t] = s2[c].y;
        }
    } else {
        for (; v < nv4; v += BLOCK_THREADS) {
            const int4 c = v2c4[v];
            o0[v] = make_float4(s2[c.x].x, s2[c.y].x, s2[c.z].x, s2[c.w].x);
        }
        for (int t = (nv4 << 2) + threadIdx.x; t < n_vertices; t += BLOCK_THREADS) {
            out[(size_t)b0 * n_vertices + t] = s2[v2c[t]].x;
        }
    }
}

extern "C" void kernel_launch(void* const* d_in, const int* in_sizes, int n_in,
                              void* d_out, int out_size)
{
    const float* x   = (const float*)d_in[0];
    const int*   v2c = (const int*)  d_in[1];
    float*       out = (float*)d_out;

    const int n_vertices = in_sizes[1];                  // 100000
    const int batch      = out_size / n_vertices;        // 1024
    const int n_clusters = in_sizes[0] / batch;          // 25000

    const int smem_bytes = 2 * n_clusters * (int)sizeof(float);  // 200000 B

    static bool attr_set = false;
    if (!attr_set) {
        cudaFuncSetAttribute(graph_reverse_pool_kernel,
                             cudaFuncAttributeMaxDynamicSharedMemorySize,
                             smem_bytes);
        attr_set = true;
    }

    const int n_pairs = (batch + 1) / 2;                 // 512 CTAs
    graph_reverse_pool_kernel<<<n_pairs, BLOCK_THREADS, smem_bytes>>>(
        x, v2c, out, batch, n_clusters, n_vertices);
}

// round 4
// speedup vs baseline: 1.1089x; 1.1089x over previous
#include <cuda_runtime.h>
#include <cstdint>

// GraphReversePool: out[b, v] = x[b, v2c[v]]
//   x   : [BATCH, N_CLUSTERS] fp32   (d_in[0])
//   v2c : [VERTICES] int32           (d_in[1])
//   out : [BATCH, VERTICES] fp32
//
// R4: ONE batch row per CTA (100 KB smem) -> 2 CTAs/SM, 64 resident warps.
// Staging of one CTA overlaps the gather of its co-resident CTA, fixing the
// exposed-latency / occupancy bottleneck seen at 200 KB smem (occ 47.7%).
// v2c L2 traffic doubles but L2 had 65% headroom. Streaming stores (.cs)
// keep the 400 MB write-once output from thrashing L2.

#define BLOCK_THREADS 1024

__global__ __launch_bounds__(BLOCK_THREADS, 2)
void graph_reverse_pool_kernel(const float* __restrict__ x,
                               const int*   __restrict__ v2c,
                               float*       __restrict__ out,
                               int batch, int n_clusters, int n_vertices)
{
    extern __shared__ float srow[];   // [n_clusters] — one batch row

    const int b = blockIdx.x;

    // ---- Stage this CTA's x row into smem (float4, fully coalesced) ----
    const int nc4 = n_clusters >> 2;           // 25000/4 = 6250, exact
    {
        const float4* __restrict__ xr = reinterpret_cast<const float4*>(x + (size_t)b * n_clusters);
        float4* __restrict__ s4 = reinterpret_cast<float4*>(srow);
        for (int i = threadIdx.x; i < nc4; i += BLOCK_THREADS) {
            s4[i] = xr[i];
        }
        // scalar tail (dead for 25000, kept for safety)
        for (int i = (nc4 << 2) + threadIdx.x; i < n_clusters; i += BLOCK_THREADS) {
            srow[i] = x[(size_t)b * n_clusters + i];
        }
    }
    __syncthreads();

    // ---- Gather: prefetched int4 v2c -> 4x LDS.32 -> 1x STG.128 (.cs) ----
    const int4* __restrict__ v2c4 = reinterpret_cast<const int4*>(v2c);
    float4* __restrict__ o = reinterpret_cast<float4*>(out + (size_t)b * n_vertices);

    const int nv4 = n_vertices >> 2;           // 100000/4 = 25000, exact

    int v = threadIdx.x;
    if (v < nv4) {
        int4 c = v2c4[v];
        int vn = v + BLOCK_THREADS;
        while (vn < nv4) {
            const int4 cn = v2c4[vn];          // prefetch next indices
            float4 a;
            a.x = srow[c.x];
            a.y = srow[c.y];
            a.z = srow[c.z];
            a.w = srow[c.w];
            __stcs(&o[v], a);                  // streaming store, bypass-ish L2
            v = vn; vn += BLOCK_THREADS;
            c = cn;
        }
        // final iteration
        float4 a;
        a.x = srow[c.x];
        a.y = srow[c.y];
        a.z = srow[c.z];
        a.w = srow[c.w];
        __stcs(&o[v], a);
    }
    // scalar vertex tail (dead for 100000)
    for (int t = (nv4 << 2) + threadIdx.x; t < n_vertices; t += BLOCK_THREADS) {
        out[(size_t)b * n_vertices + t] = srow[v2c[t]];
    }
}

extern "C" void kernel_launch(void* const* d_in, const int* in_sizes, int n_in,
                              void* d_out, int out_size)
{
    const float* x   = (const float*)d_in[0];
    const int*   v2c = (const int*)  d_in[1];
    float*       out = (float*)d_out;

    const int n_vertices = in_sizes[1];                  // 100000
    const int batch      = out_size / n_vertices;        // 1024
    const int n_clusters = in_sizes[0] / batch;          // 25000

    const int smem_bytes = n_clusters * (int)sizeof(float);  // 100000 B

    static bool attr_set = false;
    if (!attr_set) {
        cudaFuncSetAttribute(graph_reverse_pool_kernel,
                             cudaFuncAttributeMaxDynamicSharedMemorySize,
                             smem_bytes);
        attr_set = true;
    }

    graph_reverse_pool_kernel<<<batch, BLOCK_THREADS, smem_bytes>>>(
        x, v2c, out, batch, n_clusters, n_vertices);
}

// round 5
// speedup vs baseline: 1.2041x; 1.0859x over previous
#include <cuda_runtime.h>
#include <cstdint>

// GraphReversePool: out[b, v] = x[b, v2c[v]]
//   x   : [BATCH, N_CLUSTERS] fp32   (d_in[0])
//   v2c : [VERTICES] int32           (d_in[1])
//   out : [BATCH, VERTICES] fp32
//
// R5: stage the 100 KB x-row into smem with ONE cp.async.bulk (UBLKCP) —
// zero per-lane LSU work for staging, pure DMA overlapping the co-resident
// CTA's gather. Gather loop widened to 2 quads/iter for load MLP.
// 2 CTAs/SM (occ ~88%).

#define BLOCK_THREADS 1024

__device__ __forceinline__ uint32_t smem_u32(const void* p) {
    return (uint32_t)__cvta_generic_to_shared(p);
}

__global__ __launch_bounds__(BLOCK_THREADS, 2)
void graph_reverse_pool_kernel(const float* __restrict__ x,
                               const int*   __restrict__ v2c,
                               float*       __restrict__ out,
                               int batch, int n_clusters, int n_vertices)
{
    extern __shared__ __align__(16) unsigned char smem_raw[];
    float* srow = reinterpret_cast<float*>(smem_raw);

    const int b = blockIdx.x;
    const int row_bytes = n_clusters * 4;
    const int mbar_off  = (row_bytes + 15) & ~15;
    uint64_t* mbar = reinterpret_cast<uint64_t*>(smem_raw + mbar_off);
    const uint32_t mbar_addr = smem_u32(mbar);

    const float* __restrict__ xrow = x + (size_t)b * n_clusters;

    const bool can_bulk = ((row_bytes & 15) == 0) &&
                          ((((uintptr_t)xrow) & 15) == 0);

    if (can_bulk) {
        if (threadIdx.x == 0) {
            asm volatile("mbarrier.init.shared.b64 [%0], 1;"
                         :: "r"(mbar_addr) : "memory");
            asm volatile("fence.proxy.async.shared::cta;" ::: "memory");
        }
        __syncthreads();
        if (threadIdx.x == 0) {
            asm volatile("mbarrier.arrive.expect_tx.shared.b64 _, [%0], %1;"
                         :: "r"(mbar_addr), "r"((uint32_t)row_bytes) : "memory");
            asm volatile("cp.async.bulk.shared::cta.global.mbarrier::complete_tx::bytes "
                         "[%0], [%1], %2, [%3];"
                         :: "r"(smem_u32(srow)), "l"(xrow),
                            "r"((uint32_t)row_bytes), "r"(mbar_addr)
                         : "memory");
        }
        // every thread waits independently on the mbarrier (phase 0)
        uint32_t done = 0;
        while (!done) {
            asm volatile(
                "{\n\t.reg .pred p;\n\t"
                "mbarrier.try_wait.parity.acquire.cta.shared::cta.b64 p, [%1], 0, 0x989680;\n\t"
                "selp.b32 %0, 1, 0, p;\n\t}"
                : "=r"(done) : "r"(mbar_addr) : "memory");
        }
    } else {
        // fallback manual staging (not expected for this shape)
        for (int i = threadIdx.x; i < n_clusters; i += BLOCK_THREADS)
            srow[i] = xrow[i];
        __syncthreads();
    }

    // ---- Gather: 2 quads per iteration, prefetched indices, streaming stores ----
    const int4* __restrict__ v2c4 = reinterpret_cast<const int4*>(v2c);
    float4* __restrict__ o = reinterpret_cast<float4*>(out + (size_t)b * n_vertices);

    const int nv4 = n_vertices >> 2;           // 100000/4 = 25000, exact
    const int S = BLOCK_THREADS;

    int v = threadIdx.x;
    while (v + S < nv4) {
        const int4 c0 = v2c4[v];
        const int4 c1 = v2c4[v + S];
        float4 a0, a1;
        a0.x = srow[c0.x]; a0.y = srow[c0.y]; a0.z = srow[c0.z]; a0.w = srow[c0.w];
        a1.x = srow[c1.x]; a1.y = srow[c1.y]; a1.z = srow[c1.z]; a1.w = srow[c1.w];
        __stcs(&o[v],     a0);
        __stcs(&o[v + S], a1);
        v += 2 * S;
    }
    if (v < nv4) {
        const int4 c = v2c4[v];
        float4 a;
        a.x = srow[c.x]; a.y = srow[c.y]; a.z = srow[c.z]; a.w = srow[c.w];
        __stcs(&o[v], a);
    }
    // scalar vertex tail (dead for 100000, kept for safety)
    for (int t = (nv4 << 2) + threadIdx.x; t < n_vertices; t += BLOCK_THREADS) {
        out[(size_t)b * n_vertices + t] = srow[v2c[t]];
    }
}

extern "C" void kernel_launch(void* const* d_in, const int* in_sizes, int n_in,
                              void* d_out, int out_size)
{
    const float* x   = (const float*)d_in[0];
    const int*   v2c = (const int*)  d_in[1];
    float*       out = (float*)d_out;

    const int n_vertices = in_sizes[1];                  // 100000
    const int batch      = out_size / n_vertices;        // 1024
    const int n_clusters = in_sizes[0] / batch;          // 25000

    const int row_bytes  = n_clusters * (int)sizeof(float);      // 100000
    const int smem_bytes = ((row_bytes + 15) & ~15) + 16;        // row + mbarrier

    static bool attr_set = false;
    if (!attr_set) {
        cudaFuncSetAttribute(graph_reverse_pool_kernel,
                             cudaFuncAttributeMaxDynamicSharedMemorySize,
                             smem_bytes);
        attr_set = true;
    }

    graph_reverse_pool_kernel<<<batch, BLOCK_THREADS, smem_bytes>>>(
        x, v2c, out, batch, n_clusters, n_vertices);
}